// round 4
// baseline (speedup 1.0000x reference)
#include <cuda_runtime.h>
#include <cuda_bf16.h>
#include <math.h>
#include <float.h>

#define N_NODES   50000
#define N_EDGES   600000
#define NFEAT     128
#define NHID      128
#define NGRAPH    512
#define NCLASS    10
#define BN_EPS    1e-5f

// ---------------- scratch (no allocations allowed) ----------------
__device__ float g_xw[N_NODES * NHID];      // GEMM output / agg input
__device__ float g_h [N_NODES * NHID];      // layer activations
__device__ float g_dinv[N_NODES];
__device__ int   g_cnt[N_NODES];
__device__ int   g_rowptr[N_NODES + 1];
__device__ int   g_cursor[N_NODES];
__device__ int   g_esrc[N_EDGES];
__device__ float g_ew[N_EDGES];
__device__ float g_pool[NGRAPH * NHID];
__device__ float g_fc1[NGRAPH * NHID];
__device__ float g_fc2[NGRAPH * (NHID/2)];
__device__ float g_bnscale[NHID];
__device__ float g_bnbias[NHID];

// ---------------- small helpers ----------------
__device__ __forceinline__ float4 f4fma(float4 a, float s, float4 acc) {
    acc.x += a.x * s; acc.y += a.y * s; acc.z += a.z * s; acc.w += a.w * s;
    return acc;
}

__device__ __forceinline__ void atomicMaxFloat(float* addr, float v) {
    if (v >= 0.0f) atomicMax((int*)addr, __float_as_int(v));
    else           atomicMin((unsigned int*)addr, (unsigned int)__float_as_int(v));
}

// ---------------- degree / CSR build ----------------
__global__ void k_hist(const int* __restrict__ dst, int* cnt, int e) {
    int i = blockIdx.x * blockDim.x + threadIdx.x;
    if (i < e) atomicAdd(&cnt[dst[i]], 1);
}

__global__ void k_dinv(const int* __restrict__ cnt, float* dinv, int n) {
    int i = blockIdx.x * blockDim.x + threadIdx.x;
    if (i < n) dinv[i] = rsqrtf((float)cnt[i] + 1.0f);
}

// single-block scan: rowptr[i+1] = prefix sum of cnt; also seeds cursor
__global__ void k_scan(const int* __restrict__ cnt, int* rowptr, int* cursor, int n) {
    __shared__ int wsum[32];
    __shared__ int carry;
    int tid = threadIdx.x, lane = tid & 31, wid = tid >> 5;
    if (tid == 0) { carry = 0; rowptr[0] = 0; }
    __syncthreads();
    for (int base = 0; base < n; base += 1024) {
        int i = base + tid;
        int v = (i < n) ? cnt[i] : 0;
        int incl = v;
        #pragma unroll
        for (int off = 1; off < 32; off <<= 1) {
            int t = __shfl_up_sync(0xFFFFFFFFu, incl, off);
            if (lane >= off) incl += t;
        }
        if (lane == 31) wsum[wid] = incl;
        __syncthreads();
        if (wid == 0) {
            int s = wsum[lane];
            #pragma unroll
            for (int off = 1; off < 32; off <<= 1) {
                int t = __shfl_up_sync(0xFFFFFFFFu, s, off);
                if (lane >= off) s += t;
            }
            wsum[lane] = s;
        }
        __syncthreads();
        int woff = (wid > 0) ? wsum[wid - 1] : 0;
        if (i < n) {
            int excl = carry + woff + incl - v;
            rowptr[i + 1] = excl + v;
            cursor[i] = excl;
        }
        __syncthreads();
        if (tid == 0) carry += wsum[31];
        __syncthreads();
    }
}

__global__ void k_fill(const int* __restrict__ src, const int* __restrict__ dst,
                       const float* __restrict__ dinv,
                       int* cursor, int* esrc, float* ew, int e) {
    int i = blockIdx.x * blockDim.x + threadIdx.x;
    if (i < e) {
        int s = src[i], d = dst[i];
        int pos = atomicAdd(&cursor[d], 1);
        esrc[pos] = s;
        ew[pos] = dinv[s] * dinv[d];
    }
}

// ---------------- BN coefficient precompute + pool init ----------------
__global__ void k_bncoef(const float* gamma, const float* beta,
                         const float* mean, const float* var,
                         float* bnscale, float* bnbias) {
    int c = threadIdx.x;
    if (c < NHID) {
        float s = gamma[c] * rsqrtf(var[c] + BN_EPS);
        bnscale[c] = s;
        bnbias[c]  = beta[c] - mean[c] * s;
    }
}

__global__ void k_pool_init(float* pool, int n) {
    int i = blockIdx.x * blockDim.x + threadIdx.x;
    if (i < n) pool[i] = __int_as_float(0xff800000); // -inf
}

// ---------------- GEMM: C[n x 128] = A[n x 128] @ W[128 x 128] ----------------
// 256 threads, 64 rows/block. W (64KB) + A tile (32KB) in shared. 4x8 reg tile.
__global__ void __launch_bounds__(256, 2)
k_gemm(const float* __restrict__ A, const float* __restrict__ W,
       float* __restrict__ C, int n) {
    extern __shared__ float sm[];
    float* As = sm;             // [64][128]
    float* Ws = sm + 64 * 128;  // [128][128]
    int tid = threadIdx.x;
    int row0 = blockIdx.x * 64;

    const float4* W4 = (const float4*)W;
    float4* Ws4 = (float4*)Ws;
    #pragma unroll
    for (int i = 0; i < 16; i++) Ws4[tid + i * 256] = W4[tid + i * 256];

    float4* As4 = (float4*)As;
    const float4* A4 = (const float4*)A;
    #pragma unroll
    for (int i = 0; i < 8; i++) {
        int idx = tid + i * 256;          // float4 index in 64x32 tile
        int r = idx >> 5;
        int grow = row0 + r;
        float4 v = make_float4(0.f, 0.f, 0.f, 0.f);
        if (grow < n) v = A4[grow * 32 + (idx & 31)];
        As4[idx] = v;
    }
    __syncthreads();

    int tc = tid & 15;   // column group: 8 cols
    int tr = tid >> 4;   // row group: 4 rows

    float acc[4][8];
    #pragma unroll
    for (int i = 0; i < 4; i++)
        #pragma unroll
        for (int j = 0; j < 8; j++) acc[i][j] = 0.f;

    const float* AsR = As + (tr * 4) * 128;
    const float* WsC = Ws + tc * 8;

    #pragma unroll 4
    for (int k = 0; k < 128; k++) {
        float a0 = AsR[k];
        float a1 = AsR[128 + k];
        float a2 = AsR[256 + k];
        float a3 = AsR[384 + k];
        float4 w0 = *(const float4*)(WsC + k * 128);
        float4 w1 = *(const float4*)(WsC + k * 128 + 4);
        float w[8] = {w0.x, w0.y, w0.z, w0.w, w1.x, w1.y, w1.z, w1.w};
        #pragma unroll
        for (int j = 0; j < 8; j++) {
            acc[0][j] += a0 * w[j];
            acc[1][j] += a1 * w[j];
            acc[2][j] += a2 * w[j];
            acc[3][j] += a3 * w[j];
        }
    }

    #pragma unroll
    for (int i = 0; i < 4; i++) {
        int grow = row0 + tr * 4 + i;
        if (grow < n) {
            float4 o0 = make_float4(acc[i][0], acc[i][1], acc[i][2], acc[i][3]);
            float4 o1 = make_float4(acc[i][4], acc[i][5], acc[i][6], acc[i][7]);
            float4* dstp = (float4*)(C + grow * 128 + tc * 8);
            dstp[0] = o0; dstp[1] = o1;
        }
    }
}

// ---------------- aggregation (pull, warp per node) ----------------
// mode 0: out = relu(agg)   mode 1: relu(agg) -> bn -> atomicMax pool[batch]
__global__ void __launch_bounds__(256)
k_agg(const float4* __restrict__ xw, const int* __restrict__ rowptr,
      const int* __restrict__ esrc, const float* __restrict__ ew,
      const float* __restrict__ dinv, const float4* __restrict__ bias,
      float4* __restrict__ out, int n, int mode,
      const float4* __restrict__ bnscale, const float4* __restrict__ bnbias,
      const int* __restrict__ batch, float* __restrict__ pool) {
    int warp = (blockIdx.x * blockDim.x + threadIdx.x) >> 5;
    int lane = threadIdx.x & 31;
    if (warp >= n) return;

    float di = dinv[warp];
    float4 acc = f4fma(xw[warp * 32 + lane], di * di, bias[lane]);

    int beg = rowptr[warp], end = rowptr[warp + 1];
    int j = beg;
    for (; j + 4 <= end; j += 4) {
        int s0 = esrc[j],     s1 = esrc[j + 1], s2 = esrc[j + 2], s3 = esrc[j + 3];
        float w0 = ew[j],     w1 = ew[j + 1],   w2 = ew[j + 2],   w3 = ew[j + 3];
        float4 v0 = xw[s0 * 32 + lane];
        float4 v1 = xw[s1 * 32 + lane];
        float4 v2 = xw[s2 * 32 + lane];
        float4 v3 = xw[s3 * 32 + lane];
        acc = f4fma(v0, w0, acc);
        acc = f4fma(v1, w1, acc);
        acc = f4fma(v2, w2, acc);
        acc = f4fma(v3, w3, acc);
    }
    for (; j < end; j++)
        acc = f4fma(xw[esrc[j] * 32 + lane], ew[j], acc);

    // ReLU is applied in BOTH modes (reference has relu on all 3 conv layers)
    acc.x = fmaxf(acc.x, 0.f); acc.y = fmaxf(acc.y, 0.f);
    acc.z = fmaxf(acc.z, 0.f); acc.w = fmaxf(acc.w, 0.f);

    if (mode == 0) {
        out[warp * 32 + lane] = acc;
    } else {
        float4 s = bnscale[lane], b = bnbias[lane];
        acc.x = acc.x * s.x + b.x; acc.y = acc.y * s.y + b.y;
        acc.z = acc.z * s.z + b.z; acc.w = acc.w * s.w + b.w;
        int g = batch[warp];
        float* pb = pool + g * NHID + lane * 4;
        atomicMaxFloat(pb + 0, acc.x);
        atomicMaxFloat(pb + 1, acc.y);
        atomicMaxFloat(pb + 2, acc.z);
        atomicMaxFloat(pb + 3, acc.w);
    }
}

// ---------------- small FC: out[R x C] = act(in[R x K] @ W[K x C] + b) ------
__global__ void k_fc(const float* __restrict__ in, const float* __restrict__ W,
                     const float* __restrict__ b, float* __restrict__ out,
                     int K, int C, int relu) {
    __shared__ float s_in[128];
    int r = blockIdx.x;
    for (int k = threadIdx.x; k < K; k += blockDim.x) s_in[k] = in[r * K + k];
    __syncthreads();
    for (int c = threadIdx.x; c < C; c += blockDim.x) {
        float acc = b[c];
        for (int k = 0; k < K; k++) acc += s_in[k] * W[k * C + c];
        if (relu) acc = fmaxf(acc, 0.f);
        out[r * C + c] = acc;
    }
}

// ---------------- launcher ----------------
extern "C" void kernel_launch(void* const* d_in, const int* in_sizes, int n_in,
                              void* d_out, int out_size) {
    const float* x    = (const float*)d_in[0];
    const int*   ei   = (const int*)d_in[1];
    const int*   batch= (const int*)d_in[2];
    const float* W1   = (const float*)d_in[3];
    const float* b1   = (const float*)d_in[4];
    const float* W2   = (const float*)d_in[5];
    const float* b2   = (const float*)d_in[6];
    const float* W3   = (const float*)d_in[7];
    const float* b3   = (const float*)d_in[8];
    const float* gamma= (const float*)d_in[9];
    const float* beta = (const float*)d_in[10];
    const float* rmean= (const float*)d_in[11];
    const float* rvar = (const float*)d_in[12];
    const float* lw1  = (const float*)d_in[13];
    const float* lb1  = (const float*)d_in[14];
    const float* lw2  = (const float*)d_in[15];
    const float* lb2  = (const float*)d_in[16];
    const float* lw3  = (const float*)d_in[17];
    const float* lb3  = (const float*)d_in[18];
    float* out = (float*)d_out;

    const int N = in_sizes[0] / NFEAT;
    const int E = in_sizes[1] / 2;
    const int* src = ei;
    const int* dst = ei + E;

    // resolve scratch symbol addresses (non-stream API: capture-safe)
    float *p_xw, *p_h, *p_dinv, *p_ew, *p_pool, *p_fc1, *p_fc2, *p_bns, *p_bnb;
    int *p_cnt, *p_rowptr, *p_cursor, *p_esrc;
    cudaGetSymbolAddress((void**)&p_xw, g_xw);
    cudaGetSymbolAddress((void**)&p_h, g_h);
    cudaGetSymbolAddress((void**)&p_dinv, g_dinv);
    cudaGetSymbolAddress((void**)&p_cnt, g_cnt);
    cudaGetSymbolAddress((void**)&p_rowptr, g_rowptr);
    cudaGetSymbolAddress((void**)&p_cursor, g_cursor);
    cudaGetSymbolAddress((void**)&p_esrc, g_esrc);
    cudaGetSymbolAddress((void**)&p_ew, g_ew);
    cudaGetSymbolAddress((void**)&p_pool, g_pool);
    cudaGetSymbolAddress((void**)&p_fc1, g_fc1);
    cudaGetSymbolAddress((void**)&p_fc2, g_fc2);
    cudaGetSymbolAddress((void**)&p_bns, g_bnscale);
    cudaGetSymbolAddress((void**)&p_bnb, g_bnbias);

    const int gemm_smem = (64 * 128 + 128 * 128) * (int)sizeof(float); // 96KB
    cudaFuncSetAttribute(k_gemm, cudaFuncAttributeMaxDynamicSharedMemorySize, gemm_smem);

    // ---- CSR build ----
    cudaMemsetAsync(p_cnt, 0, N * sizeof(int));
    k_hist<<<(E + 255) / 256, 256>>>(dst, p_cnt, E);
    k_dinv<<<(N + 255) / 256, 256>>>(p_cnt, p_dinv, N);
    k_scan<<<1, 1024>>>(p_cnt, p_rowptr, p_cursor, N);
    k_fill<<<(E + 255) / 256, 256>>>(src, dst, p_dinv, p_cursor, p_esrc, p_ew, E);

    // ---- BN coefficients, pool init ----
    k_bncoef<<<1, 128>>>(gamma, beta, rmean, rvar, p_bns, p_bnb);
    k_pool_init<<<(NGRAPH * NHID + 255) / 256, 256>>>(p_pool, NGRAPH * NHID);

    const int gemm_grid = (N + 63) / 64;
    const int agg_grid  = (N * 32 + 255) / 256;

    // ---- layer 1 ----
    k_gemm<<<gemm_grid, 256, gemm_smem>>>(x, W1, p_xw, N);
    k_agg<<<agg_grid, 256>>>((const float4*)p_xw, p_rowptr, p_esrc, p_ew, p_dinv,
                             (const float4*)b1, (float4*)p_h, N, 0,
                             nullptr, nullptr, nullptr, nullptr);
    // ---- layer 2 ----
    k_gemm<<<gemm_grid, 256, gemm_smem>>>(p_h, W2, p_xw, N);
    k_agg<<<agg_grid, 256>>>((const float4*)p_xw, p_rowptr, p_esrc, p_ew, p_dinv,
                             (const float4*)b2, (float4*)p_h, N, 0,
                             nullptr, nullptr, nullptr, nullptr);
    // ---- layer 3 + ReLU + BN + pool ----
    k_gemm<<<gemm_grid, 256, gemm_smem>>>(p_h, W3, p_xw, N);
    k_agg<<<agg_grid, 256>>>((const float4*)p_xw, p_rowptr, p_esrc, p_ew, p_dinv,
                             (const float4*)b3, nullptr, N, 1,
                             (const float4*)p_bns, (const float4*)p_bnb, batch, p_pool);

    // ---- MLP head ----
    k_fc<<<NGRAPH, 128>>>(p_pool, lw1, lb1, p_fc1, NHID, NHID, 1);
    k_fc<<<NGRAPH, 64>>>(p_fc1, lw2, lb2, p_fc2, NHID, NHID / 2, 1);
    k_fc<<<NGRAPH, 32>>>(p_fc2, lw3, lb3, out, NHID / 2, NCLASS, 0);
}